// round 1
// baseline (speedup 1.0000x reference)
#include <cuda_runtime.h>
#include <cstdint>

// Problem constants
#define NE    1024          // number of codes
#define DDIM  64            // embedding dim
#define HW    4096          // H*W
#define NPIX  131072        // B*H*W
#define QELEMS (NPIX * DDIM) // 8388608
#define TILE  64            // codes per smem tile
#define NTILES (NE / TILE)  // 16
#define BLK   128           // threads per block
#define PXB   256           // pixels per block (2 per thread)
#define GRID  (NPIX / PXB)  // 512

// Device scratch (no allocations allowed)
__device__ float      g_codeT[NE * DDIM];        // codebook transposed [code][dim], 256 KB
__device__ float4     g_codeDup[NE * 32];        // per code: 32 float4 of (e_d,e_d,e_{d+1},e_{d+1}), 512 KB
__device__ float      g_halfnorm[NE];            // 0.5 * ||e_j||^2
__device__ float      g_partial[GRID];           // per-block loss partials

#define FMA2(d, a, b, c) asm("fma.rn.f32x2 %0, %1, %2, %3;" : "=l"(d) : "l"(a), "l"(b), "l"(c))
#define ADD2(d, a, b)    asm("add.rn.f32x2 %0, %1, %2;"     : "=l"(d) : "l"(a), "l"(b))

__device__ __forceinline__ unsigned long long pack2(float a, float b) {
    unsigned long long r;
    asm("mov.b64 %0, {%1, %2};" : "=l"(r) : "f"(a), "f"(b));
    return r;
}
__device__ __forceinline__ float lo32(unsigned long long v) {
    return __uint_as_float((unsigned int)v);
}
__device__ __forceinline__ float hi32(unsigned long long v) {
    return __uint_as_float((unsigned int)(v >> 32));
}

// ---------------------------------------------------------------------------
// Prep: build codeT (transposed codebook), duplicated-pair codebook, halfnorms
// embed layout: [DDIM, NE] row-major -> embed[d*NE + j]
// ---------------------------------------------------------------------------
__global__ void prep_kernel(const float* __restrict__ embed) {
    int j = blockIdx.x * blockDim.x + threadIdx.x;
    if (j >= NE) return;
    float hn = 0.f;
#pragma unroll
    for (int d = 0; d < DDIM; d += 2) {
        float v0 = embed[d * NE + j];        // coalesced across j
        float v1 = embed[(d + 1) * NE + j];
        g_codeT[j * DDIM + d]     = v0;
        g_codeT[j * DDIM + d + 1] = v1;
        g_codeDup[j * 32 + (d >> 1)] = make_float4(v0, v0, v1, v1);
        hn += v0 * v0 + v1 * v1;
    }
    g_halfnorm[j] = 0.5f * hn;
}

// ---------------------------------------------------------------------------
// Main: each thread handles 2 pixels packed in f32x2; codes stream from smem
// as pre-duplicated pairs. score_j = f.e_j - 0.5*||e_j||^2, take argmax.
// ---------------------------------------------------------------------------
__global__ void __launch_bounds__(BLK, 3) vq_main(const float* __restrict__ x,
                                                  float* __restrict__ out) {
    __shared__ float4 sDup[TILE * 32];   // 32 KB
    __shared__ float  sHN[TILE];
    __shared__ float  sRed[BLK / 32];

    const int t   = threadIdx.x;
    const int P0  = blockIdx.x * PXB;    // 256 pixels, always within one batch image
    const int b   = P0 >> 12;            // / 4096
    const int hw0 = P0 & 4095;

    const float* xb = x + (size_t)b * DDIM * HW + hw0;

    // Load 2 pixel vectors, pack component-wise into f32x2 registers
    unsigned long long F[DDIM];
#pragma unroll
    for (int d = 0; d < DDIM; d++) {
        float a = xb[d * HW + t];          // pixel A (coalesced)
        float c = xb[d * HW + 128 + t];    // pixel B (coalesced)
        F[d] = pack2(a, c);
    }

    float best0 = -1e30f, best1 = -1e30f;
    int   idx0 = 0, idx1 = 0;

    for (int tile = 0; tile < NTILES; tile++) {
        __syncthreads();
        const float4* gsrc = g_codeDup + tile * TILE * 32;
#pragma unroll 4
        for (int i = t; i < TILE * 32; i += BLK) sDup[i] = gsrc[i];
        if (t < TILE) sHN[t] = g_halfnorm[tile * TILE + t];
        __syncthreads();

#pragma unroll 1
        for (int c = 0; c < TILE; c++) {
            const ulonglong2* cp = reinterpret_cast<const ulonglong2*>(sDup + c * 32);
            unsigned long long a0 = 0ull, a1 = 0ull, a2 = 0ull, a3 = 0ull;
#pragma unroll
            for (int k = 0; k < 16; k++) {
                ulonglong2 e0 = cp[2 * k];
                ulonglong2 e1 = cp[2 * k + 1];
                FMA2(a0, F[4 * k + 0], e0.x, a0);
                FMA2(a1, F[4 * k + 1], e0.y, a1);
                FMA2(a2, F[4 * k + 2], e1.x, a2);
                FMA2(a3, F[4 * k + 3], e1.y, a3);
            }
            ADD2(a0, a0, a1);
            ADD2(a2, a2, a3);
            ADD2(a0, a0, a2);
            float d0 = lo32(a0), d1 = hi32(a0);
            float hn = sHN[c];
            float s0 = d0 - hn;
            float s1 = d1 - hn;
            int   j  = tile * TILE + c;
            if (s0 > best0) { best0 = s0; idx0 = j; }  // strict > keeps lowest index on ties
            if (s1 > best1) { best1 = s1; idx1 = j; }
        }
    }

    // Epilogue: gather selected code vectors, write quantized output (B,D,H,W),
    // accumulate exact fp32 loss sum.
    float* ob = out + (size_t)b * DDIM * HW + hw0;
    float loss = 0.f;

    const float4* c0 = reinterpret_cast<const float4*>(g_codeT + idx0 * DDIM);
#pragma unroll
    for (int k = 0; k < 16; k++) {
        float4 q = c0[k];
        int d = 4 * k;
        float r;
        ob[(d + 0) * HW + t] = q.x; r = q.x - lo32(F[d + 0]); loss += r * r;
        ob[(d + 1) * HW + t] = q.y; r = q.y - lo32(F[d + 1]); loss += r * r;
        ob[(d + 2) * HW + t] = q.z; r = q.z - lo32(F[d + 2]); loss += r * r;
        ob[(d + 3) * HW + t] = q.w; r = q.w - lo32(F[d + 3]); loss += r * r;
    }
    const float4* c1 = reinterpret_cast<const float4*>(g_codeT + idx1 * DDIM);
#pragma unroll
    for (int k = 0; k < 16; k++) {
        float4 q = c1[k];
        int d = 4 * k;
        float r;
        ob[(d + 0) * HW + 128 + t] = q.x; r = q.x - hi32(F[d + 0]); loss += r * r;
        ob[(d + 1) * HW + 128 + t] = q.y; r = q.y - hi32(F[d + 1]); loss += r * r;
        ob[(d + 2) * HW + 128 + t] = q.z; r = q.z - hi32(F[d + 2]); loss += r * r;
        ob[(d + 3) * HW + 128 + t] = q.w; r = q.w - hi32(F[d + 3]); loss += r * r;
    }

    // Block loss reduction
#pragma unroll
    for (int o = 16; o; o >>= 1) loss += __shfl_xor_sync(0xFFFFFFFFu, loss, o);
    if ((t & 31) == 0) sRed[t >> 5] = loss;
    __syncthreads();
    if (t == 0) {
        float s = 0.f;
#pragma unroll
        for (int w = 0; w < BLK / 32; w++) s += sRed[w];
        g_partial[blockIdx.x] = s;
    }
}

// ---------------------------------------------------------------------------
// Finalize: reduce 512 partials, write mean loss to out[last]
// ---------------------------------------------------------------------------
__global__ void fin_kernel(float* __restrict__ out, int last) {
    __shared__ float sRed[GRID / 32];
    int t = threadIdx.x;  // 512 threads
    float v = g_partial[t];
#pragma unroll
    for (int o = 16; o; o >>= 1) v += __shfl_xor_sync(0xFFFFFFFFu, v, o);
    if ((t & 31) == 0) sRed[t >> 5] = v;
    __syncthreads();
    if (t == 0) {
        double s = 0.0;
#pragma unroll
        for (int w = 0; w < GRID / 32; w++) s += (double)sRed[w];
        out[last] = (float)(s / (double)QELEMS);
    }
}

// ---------------------------------------------------------------------------
extern "C" void kernel_launch(void* const* d_in, const int* in_sizes, int n_in,
                              void* d_out, int out_size) {
    const float* x     = (const float*)d_in[0];
    const float* embed = (const float*)d_in[1];
    // Defensive: if input order is swapped, detect by size (x has 8.4M elems, embed 65536)
    if (n_in >= 2 && in_sizes[0] == NE * DDIM && in_sizes[1] == QELEMS) {
        const float* tmp = x; x = embed; embed = tmp;
    }
    float* out = (float*)d_out;

    prep_kernel<<<4, 256>>>(embed);
    vq_main<<<GRID, BLK>>>(x, out);
    fin_kernel<<<1, GRID>>>(out, out_size - 1);
}

// round 2
// speedup vs baseline: 1.5190x; 1.5190x over previous
#include <cuda_runtime.h>
#include <cstdint>

// Problem constants
#define NE    1024
#define DDIM  64
#define HW    4096
#define NPIX  131072
#define QELEMS (NPIX * DDIM)
#define TILE  64            // codes per smem tile
#define NTILES (NE / TILE)  // 16
#define TILE_FLOATS (TILE * DDIM)   // 4096 floats = 16 KB
#define BLK   128
#define PXB   256           // pixels per block (2 per thread)
#define GRID  (NPIX / PXB)  // 512

__device__ float g_codeT[NE * DDIM];   // codebook transposed [code][dim] (tile source + gather)
__device__ float g_halfnorm[NE];       // 0.5 * ||e_j||^2
__device__ float g_partial[GRID];

#define FMA2(d, a, b, c) asm("fma.rn.f32x2 %0, %1, %2, %3;" : "=l"(d) : "l"(a), "l"(b), "l"(c))
#define ADD2(d, a, b)    asm("add.rn.f32x2 %0, %1, %2;"     : "=l"(d) : "l"(a), "l"(b))

__device__ __forceinline__ unsigned long long pack2(float a, float b) {
    unsigned long long r;
    asm("mov.b64 %0, {%1, %2};" : "=l"(r) : "f"(a), "f"(b));
    return r;
}
__device__ __forceinline__ float lo32(unsigned long long v) {
    return __uint_as_float((unsigned int)v);
}
__device__ __forceinline__ float hi32(unsigned long long v) {
    return __uint_as_float((unsigned int)(v >> 32));
}
__device__ __forceinline__ void cpasync16(unsigned int saddr, const void* gptr) {
    asm volatile("cp.async.cg.shared.global [%0], [%1], 16;" :: "r"(saddr), "l"(gptr));
}
__device__ __forceinline__ void cpasync_commit() {
    asm volatile("cp.async.commit_group;");
}
template <int N>
__device__ __forceinline__ void cpasync_wait() {
    asm volatile("cp.async.wait_group %0;" :: "n"(N));
}

// ---------------------------------------------------------------------------
// Prep: transpose codebook, compute halfnorms. embed layout [DDIM, NE].
// ---------------------------------------------------------------------------
__global__ void prep_kernel(const float* __restrict__ embed) {
    int j = blockIdx.x * blockDim.x + threadIdx.x;
    if (j >= NE) return;
    float hn = 0.f;
#pragma unroll
    for (int d = 0; d < DDIM; d++) {
        float v = embed[d * NE + j];   // coalesced across j
        g_codeT[j * DDIM + d] = v;
        hn += v * v;
    }
    g_halfnorm[j] = 0.5f * hn;
}

// ---------------------------------------------------------------------------
// Main kernel. Each thread: 2 pixels, dims packed pairwise into f32x2.
// score_j = f.e_j - 0.5||e_j||^2 -> argmax. One LDS.128 feeds 4 FFMA2.
// ---------------------------------------------------------------------------
__global__ void __launch_bounds__(BLK, 2) vq_main(const float* __restrict__ x,
                                                  float* __restrict__ out) {
    __shared__ float sCode[2][TILE_FLOATS];  // 2 x 16 KB double buffer
    __shared__ float sHN[NE];                // 4 KB
    __shared__ float sRed[BLK / 32];

    const int t   = threadIdx.x;
    const int P0  = blockIdx.x * PXB;
    const int b   = P0 >> 12;
    const int hw0 = P0 & 4095;

    const float* xb = x + (size_t)b * DDIM * HW + hw0;

    // Stage halfnorms into smem
#pragma unroll
    for (int i = t; i < NE; i += BLK) sHN[i] = g_halfnorm[i];

    // Kick off async load of tile 0
    {
        unsigned int sbase = (unsigned int)__cvta_generic_to_shared(&sCode[0][0]);
        const float4* gsrc = reinterpret_cast<const float4*>(g_codeT);
#pragma unroll
        for (int i = 0; i < TILE_FLOATS / 4; i += BLK)
            cpasync16(sbase + (i + t) * 16, gsrc + i + t);
        cpasync_commit();
    }

    // Load 2 pixel vectors; pack adjacent dims: FA[j] = (f_{2j}, f_{2j+1})
    unsigned long long FA[DDIM / 2], FB[DDIM / 2];
#pragma unroll
    for (int j = 0; j < DDIM / 2; j++) {
        float a0 = xb[(2 * j) * HW + t];
        float a1 = xb[(2 * j + 1) * HW + t];
        float b0 = xb[(2 * j) * HW + 128 + t];
        float b1 = xb[(2 * j + 1) * HW + 128 + t];
        FA[j] = pack2(a0, a1);
        FB[j] = pack2(b0, b1);
    }

    float best0 = -1e30f, best1 = -1e30f;
    int   idx0 = 0, idx1 = 0;

    for (int tile = 0; tile < NTILES; tile++) {
        // Prefetch next tile into the other buffer
        if (tile + 1 < NTILES) {
            unsigned int sbase = (unsigned int)__cvta_generic_to_shared(&sCode[(tile + 1) & 1][0]);
            const float4* gsrc = reinterpret_cast<const float4*>(g_codeT + (tile + 1) * TILE_FLOATS);
#pragma unroll
            for (int i = 0; i < TILE_FLOATS / 4; i += BLK)
                cpasync16(sbase + (i + t) * 16, gsrc + i + t);
            cpasync_commit();
            cpasync_wait<1>();
        } else {
            cpasync_wait<0>();
        }
        __syncthreads();

        const float* cbuf = sCode[tile & 1];
#pragma unroll 1
        for (int c = 0; c < TILE; c++) {
            const ulonglong2* cp = reinterpret_cast<const ulonglong2*>(cbuf + c * DDIM);
            unsigned long long aA0 = 0ull, aA1 = 0ull, aA2 = 0ull, aA3 = 0ull;
            unsigned long long aB0 = 0ull, aB1 = 0ull, aB2 = 0ull, aB3 = 0ull;
#pragma unroll
            for (int k = 0; k < 16; k += 2) {
                ulonglong2 e0 = cp[k];      // dims [4k, 4k+4)
                ulonglong2 e1 = cp[k + 1];  // dims [4k+4, 4k+8)
                FMA2(aA0, FA[2 * k + 0], e0.x, aA0);
                FMA2(aB0, FB[2 * k + 0], e0.x, aB0);
                FMA2(aA1, FA[2 * k + 1], e0.y, aA1);
                FMA2(aB1, FB[2 * k + 1], e0.y, aB1);
                FMA2(aA2, FA[2 * k + 2], e1.x, aA2);
                FMA2(aB2, FB[2 * k + 2], e1.x, aB2);
                FMA2(aA3, FA[2 * k + 3], e1.y, aA3);
                FMA2(aB3, FB[2 * k + 3], e1.y, aB3);
            }
            ADD2(aA0, aA0, aA1);
            ADD2(aA2, aA2, aA3);
            ADD2(aB0, aB0, aB1);
            ADD2(aB2, aB2, aB3);
            ADD2(aA0, aA0, aA2);
            ADD2(aB0, aB0, aB2);
            float hn = sHN[tile * TILE + c];
            float s0 = lo32(aA0) + hi32(aA0) - hn;
            float s1 = lo32(aB0) + hi32(aB0) - hn;
            int   j  = tile * TILE + c;
            if (s0 > best0) { best0 = s0; idx0 = j; }
            if (s1 > best1) { best1 = s1; idx1 = j; }
        }
        __syncthreads();   // all warps done with this buffer before it is reloaded
    }

    // Epilogue: gather codes, write quantized output, exact fp32 loss sum
    float* ob = out + (size_t)b * DDIM * HW + hw0;
    float loss = 0.f;

    const float4* c0 = reinterpret_cast<const float4*>(g_codeT + idx0 * DDIM);
#pragma unroll
    for (int k = 0; k < 16; k++) {
        float4 q = c0[k];
        int d = 4 * k;
        float r;
        ob[(d + 0) * HW + t] = q.x; r = q.x - lo32(FA[2 * k]);     loss += r * r;
        ob[(d + 1) * HW + t] = q.y; r = q.y - hi32(FA[2 * k]);     loss += r * r;
        ob[(d + 2) * HW + t] = q.z; r = q.z - lo32(FA[2 * k + 1]); loss += r * r;
        ob[(d + 3) * HW + t] = q.w; r = q.w - hi32(FA[2 * k + 1]); loss += r * r;
    }
    const float4* c1 = reinterpret_cast<const float4*>(g_codeT + idx1 * DDIM);
#pragma unroll
    for (int k = 0; k < 16; k++) {
        float4 q = c1[k];
        int d = 4 * k;
        float r;
        ob[(d + 0) * HW + 128 + t] = q.x; r = q.x - lo32(FB[2 * k]);     loss += r * r;
        ob[(d + 1) * HW + 128 + t] = q.y; r = q.y - hi32(FB[2 * k]);     loss += r * r;
        ob[(d + 2) * HW + 128 + t] = q.z; r = q.z - lo32(FB[2 * k + 1]); loss += r * r;
        ob[(d + 3) * HW + 128 + t] = q.w; r = q.w - hi32(FB[2 * k + 1]); loss += r * r;
    }

#pragma unroll
    for (int o = 16; o; o >>= 1) loss += __shfl_xor_sync(0xFFFFFFFFu, loss, o);
    if ((t & 31) == 0) sRed[t >> 5] = loss;
    __syncthreads();
    if (t == 0) {
        float s = 0.f;
#pragma unroll
        for (int w = 0; w < BLK / 32; w++) s += sRed[w];
        g_partial[blockIdx.x] = s;
    }
}

// ---------------------------------------------------------------------------
__global__ void fin_kernel(float* __restrict__ out, int last) {
    __shared__ float sRed[GRID / 32];
    int t = threadIdx.x;  // 512 threads
    float v = g_partial[t];
#pragma unroll
    for (int o = 16; o; o >>= 1) v += __shfl_xor_sync(0xFFFFFFFFu, v, o);
    if ((t & 31) == 0) sRed[t >> 5] = v;
    __syncthreads();
    if (t == 0) {
        double s = 0.0;
#pragma unroll
        for (int w = 0; w < GRID / 32; w++) s += (double)sRed[w];
        out[last] = (float)(s / (double)QELEMS);
    }
}

// ---------------------------------------------------------------------------
extern "C" void kernel_launch(void* const* d_in, const int* in_sizes, int n_in,
                              void* d_out, int out_size) {
    const float* x     = (const float*)d_in[0];
    const float* embed = (const float*)d_in[1];
    if (n_in >= 2 && in_sizes[0] == NE * DDIM && in_sizes[1] == QELEMS) {
        const float* tmp = x; x = embed; embed = tmp;
    }
    float* out = (float*)d_out;

    prep_kernel<<<4, 256>>>(embed);
    vq_main<<<GRID, BLK>>>(x, out);
    fin_kernel<<<1, GRID>>>(out, out_size - 1);
}